// round 4
// baseline (speedup 1.0000x reference)
#include <cuda_runtime.h>
#include <math.h>

#define D_DIM 1024
#define F_DIM 4096
#define E_DIM 8
#define NTOK  16384               // B*S
#define NCH   512                 // chunks over F for kernel A
#define ROWS_PER_CH (F_DIM/NCH)   // 8
#define NG    16                  // stage-1 groups
#define CH_PER_G (NCH/NG)         // 32

// ---------------- device scratch ----------------
__device__ __align__(16) float g_part [NCH][5][D_DIM];   // ~10.5 MB
__device__ __align__(16) float g_part2[NG ][5][D_DIM];
__device__ __align__(16) float g_stats[5][D_DIM];        // mb, md, cbb, cbd, cdd
__device__ float g_bias_mean;

__device__ __forceinline__ void acc4(float4& s, float4 v)           { s.x += v.x; s.y += v.y; s.z += v.z; s.w += v.w; }
__device__ __forceinline__ void fma4(float4& s, float4 a, float4 b) { s.x = fmaf(a.x,b.x,s.x); s.y = fmaf(a.y,b.y,s.y); s.z = fmaf(a.z,b.z,s.z); s.w = fmaf(a.w,b.w,s.w); }

// ---------------- kernel A: column stats of W_base / W_delta -------------
// grid NCH=512, block 256. Thread = one float4 column; 8 rows x 2 mats = 16
// float4 loads, fully unrolled for deep MLP. Reg-capped for 3 blocks/SM.
__global__ void __launch_bounds__(256, 3) k_reduceW(const float* __restrict__ Wb,
                                                    const float* __restrict__ Wd) {
    const int q = threadIdx.x;    // float4 column 0..255
    const size_t base = (size_t)blockIdx.x * ROWS_PER_CH * 256 + q;
    const float4* pb = reinterpret_cast<const float4*>(Wb) + base;
    const float4* pd = reinterpret_cast<const float4*>(Wd) + base;
    float4 sb = {0,0,0,0}, sd = {0,0,0,0}, sbb = {0,0,0,0}, sbd = {0,0,0,0}, sdd = {0,0,0,0};
#pragma unroll
    for (int i = 0; i < ROWS_PER_CH; i++) {
        float4 b = pb[(size_t)i * 256];
        float4 w = pd[(size_t)i * 256];
        acc4(sb, b); acc4(sd, w);
        fma4(sbb, b, b); fma4(sbd, b, w); fma4(sdd, w, w);
    }
    const int c = blockIdx.x;
    *reinterpret_cast<float4*>(&g_part[c][0][q*4]) = sb;
    *reinterpret_cast<float4*>(&g_part[c][1][q*4]) = sd;
    *reinterpret_cast<float4*>(&g_part[c][2][q*4]) = sbb;
    *reinterpret_cast<float4*>(&g_part[c][3][q*4]) = sbd;
    *reinterpret_cast<float4*>(&g_part[c][4][q*4]) = sdd;
}

// ---------------- kernel B1: stage-1 chunk reduce --------------------------
// grid (10, NG), block 128. Thread = one (stat k, f4col q) pair within group g.
// 32 float4 loads per thread, 20480 threads total.
__global__ void __launch_bounds__(128) k_reduce1(void) {
    const int item = blockIdx.x * 128 + threadIdx.x;   // 0..1279
    const int k = item >> 8;                            // stat 0..4
    const int q = item & 255;                           // f4col 0..255
    const int g = blockIdx.y;
    float4 s = make_float4(0,0,0,0);
#pragma unroll
    for (int c = g * CH_PER_G; c < (g + 1) * CH_PER_G; c++)
        acc4(s, *reinterpret_cast<const float4*>(&g_part[c][k][q*4]));
    *reinterpret_cast<float4*>(&g_part2[g][k][q*4]) = s;
}

// ---------------- kernel B2: finalize centered stats + bias mean -----------
// grid 8, block 32. Thread = one f4col, loads all 5 stats x 16 groups (L2-hot),
// centers, writes g_stats. Block 0 warp also reduces bias.
__global__ void k_finalize(const float* __restrict__ bias) {
    const int q = blockIdx.x * 32 + threadIdx.x;
    float4 s[5];
#pragma unroll
    for (int k = 0; k < 5; k++) s[k] = make_float4(0,0,0,0);
#pragma unroll
    for (int g = 0; g < NG; g++) {
#pragma unroll
        for (int k = 0; k < 5; k++)
            acc4(s[k], *reinterpret_cast<const float4*>(&g_part2[g][k][q*4]));
    }
    const float inv = 1.0f / (float)F_DIM;
    float4 mb, md, cbb, cbd, cdd;
    mb.x = s[0].x*inv; mb.y = s[0].y*inv; mb.z = s[0].z*inv; mb.w = s[0].w*inv;
    md.x = s[1].x*inv; md.y = s[1].y*inv; md.z = s[1].z*inv; md.w = s[1].w*inv;
    cbb.x = s[2].x*inv - mb.x*mb.x; cbb.y = s[2].y*inv - mb.y*mb.y;
    cbb.z = s[2].z*inv - mb.z*mb.z; cbb.w = s[2].w*inv - mb.w*mb.w;
    cbd.x = s[3].x*inv - mb.x*md.x; cbd.y = s[3].y*inv - mb.y*md.y;
    cbd.z = s[3].z*inv - mb.z*md.z; cbd.w = s[3].w*inv - mb.w*md.w;
    cdd.x = s[4].x*inv - md.x*md.x; cdd.y = s[4].y*inv - md.y*md.y;
    cdd.z = s[4].z*inv - md.z*md.z; cdd.w = s[4].w*inv - md.w*md.w;
    *reinterpret_cast<float4*>(&g_stats[0][q*4]) = mb;
    *reinterpret_cast<float4*>(&g_stats[1][q*4]) = md;
    *reinterpret_cast<float4*>(&g_stats[2][q*4]) = cbb;
    *reinterpret_cast<float4*>(&g_stats[3][q*4]) = cbd;
    *reinterpret_cast<float4*>(&g_stats[4][q*4]) = cdd;

    if (blockIdx.x == 0) {
        const float4* b4 = reinterpret_cast<const float4*>(bias);
        float s0 = 0.f;
#pragma unroll
        for (int i = threadIdx.x; i < F_DIM / 4; i += 32) {
            float4 v = b4[i];
            s0 += (v.x + v.y) + (v.z + v.w);
        }
#pragma unroll
        for (int o = 16; o > 0; o >>= 1) s0 += __shfl_xor_sync(0xffffffffu, s0, o);
        if (threadIdx.x == 0) g_bias_mean = s0 * inv;
    }
}

// ---------------- kernel C: fused router (5-dot) ---------------------------
// 256-thread blocks, warp handles 4 tokens, scalar f32 accumulators,
// FULL unroll over chunks (deep LDG pipelining), stats via __ldg (L1-hot).
__global__ void __launch_bounds__(256, 3) k_router(const float* __restrict__ x,
                                                   const float* __restrict__ alpha,
                                                   const float* __restrict__ beta,
                                                   float* __restrict__ out) {
    __shared__ float sred[8][4][5];

    const int lane = threadIdx.x & 31;
    const int wid  = threadIdx.x >> 5;
    const int tok0 = (blockIdx.x * 8 + wid) * 4;
    const float* xp = x + (size_t)tok0 * D_DIM;

    float a0[4], a1[4], a2[4], a3[4], a4[4];
#pragma unroll
    for (int t = 0; t < 4; t++) { a0[t]=0.f; a1[t]=0.f; a2[t]=0.f; a3[t]=0.f; a4[t]=0.f; }

#pragma unroll
    for (int c = 0; c < 8; c++) {
        const int off = c * 128 + lane * 4;
        float4 xv0 = *reinterpret_cast<const float4*>(xp + 0 * D_DIM + off);
        float4 xv1 = *reinterpret_cast<const float4*>(xp + 1 * D_DIM + off);
        float4 xv2 = *reinterpret_cast<const float4*>(xp + 2 * D_DIM + off);
        float4 xv3 = *reinterpret_cast<const float4*>(xp + 3 * D_DIM + off);
        float4 s0 = __ldg(reinterpret_cast<const float4*>(&g_stats[0][off]));
        float4 s1 = __ldg(reinterpret_cast<const float4*>(&g_stats[1][off]));
        float4 s2 = __ldg(reinterpret_cast<const float4*>(&g_stats[2][off]));
        float4 s3 = __ldg(reinterpret_cast<const float4*>(&g_stats[3][off]));
        float4 s4 = __ldg(reinterpret_cast<const float4*>(&g_stats[4][off]));
        float4 xv[4] = {xv0, xv1, xv2, xv3};
#pragma unroll
        for (int t = 0; t < 4; t++) {
            float4 v = xv[t];
            float4 q;
            q.x = v.x * v.x; q.y = v.y * v.y; q.z = v.z * v.z; q.w = v.w * v.w;
            a0[t] = fmaf(v.x, s0.x, fmaf(v.y, s0.y, fmaf(v.z, s0.z, fmaf(v.w, s0.w, a0[t]))));
            a1[t] = fmaf(v.x, s1.x, fmaf(v.y, s1.y, fmaf(v.z, s1.z, fmaf(v.w, s1.w, a1[t]))));
            a2[t] = fmaf(q.x, s2.x, fmaf(q.y, s2.y, fmaf(q.z, s2.z, fmaf(q.w, s2.w, a2[t]))));
            a3[t] = fmaf(q.x, s3.x, fmaf(q.y, s3.y, fmaf(q.z, s3.z, fmaf(q.w, s3.w, a3[t]))));
            a4[t] = fmaf(q.x, s4.x, fmaf(q.y, s4.y, fmaf(q.z, s4.z, fmaf(q.w, s4.w, a4[t]))));
        }
    }

    // warp reductions: 20 independent shuffle chains per warp
#pragma unroll
    for (int t = 0; t < 4; t++) {
        float v0 = a0[t], v1 = a1[t], v2 = a2[t], v3 = a3[t], v4 = a4[t];
#pragma unroll
        for (int o = 16; o > 0; o >>= 1) {
            v0 += __shfl_xor_sync(0xffffffffu, v0, o);
            v1 += __shfl_xor_sync(0xffffffffu, v1, o);
            v2 += __shfl_xor_sync(0xffffffffu, v2, o);
            v3 += __shfl_xor_sync(0xffffffffu, v3, o);
            v4 += __shfl_xor_sync(0xffffffffu, v4, o);
        }
        if (lane == t * 5 + 0) sred[wid][t][0] = v0;
        if (lane == t * 5 + 1) sred[wid][t][1] = v1;
        if (lane == t * 5 + 2) sred[wid][t][2] = v2;
        if (lane == t * 5 + 3) sred[wid][t][3] = v3;
        if (lane == t * 5 + 4) sred[wid][t][4] = v4;
    }
    __syncthreads();

    // epilogue: one thread per token (32 tokens/block)
    if (threadIdx.x < 32) {
        const int w = threadIdx.x >> 2;
        const int t = threadIdx.x & 3;
        const int tok = blockIdx.x * 32 + threadIdx.x;
        const float bm = g_bias_mean;

        const float d_mb = sred[w][t][0];
        const float d_md = sred[w][t][1];
        const float d_bb = sred[w][t][2];
        const float d_bd = sred[w][t][3];
        const float d_dd = sred[w][t][4];

        float l[E_DIM];
#pragma unroll
        for (int e = 0; e < E_DIM; e++) {
            float a = __ldg(&alpha[e]);
            float b = __ldg(&beta[e]);
            float mu = fmaf(a, d_mb, fmaf(b, d_md, bm));
            float va = fmaf(a * a, d_bb, fmaf(2.0f * a * b, d_bd, b * b * d_dd));
            float z  = mu * rsqrtf(va + 1e-8f) * 0.70710678118654752f;
            l[e] = erff(z);
        }

        // top-2 (strict >, ties keep lower index — matches lax.top_k)
        int i1 = -1, i2 = -1;
        float v1 = -2.0f, v2 = -2.0f;
#pragma unroll
        for (int e = 0; e < E_DIM; e++) {
            float val = l[e];
            if (val > v1)      { v2 = v1; i2 = i1; v1 = val; i1 = e; }
            else if (val > v2) { v2 = val; i2 = e; }
        }
        float w2 = 1.0f / (1.0f + expf(v1 - v2));
        float w1 = 1.0f - w2;

        float wv[E_DIM];
#pragma unroll
        for (int e = 0; e < E_DIM; e++)
            wv[e] = (e == i1) ? w1 : ((e == i2) ? w2 : 0.0f);

        float4* ow = reinterpret_cast<float4*>(out + (size_t)tok * E_DIM);
        ow[0] = make_float4(wv[0], wv[1], wv[2], wv[3]);
        ow[1] = make_float4(wv[4], wv[5], wv[6], wv[7]);
        float4* ol = reinterpret_cast<float4*>(out + (size_t)NTOK * E_DIM + (size_t)tok * E_DIM);
        ol[0] = make_float4(l[0], l[1], l[2], l[3]);
        ol[1] = make_float4(l[4], l[5], l[6], l[7]);
    }
}

// ---------------- launch ---------------------------------------------------
extern "C" void kernel_launch(void* const* d_in, const int* in_sizes, int n_in,
                              void* d_out, int out_size) {
    const float* x     = (const float*)d_in[0];
    const float* Wb    = (const float*)d_in[1];
    const float* Wd    = (const float*)d_in[2];
    const float* bias  = (const float*)d_in[3];
    const float* alpha = (const float*)d_in[4];
    const float* beta  = (const float*)d_in[5];
    float* out = (float*)d_out;

    k_reduceW<<<NCH, 256>>>(Wb, Wd);
    k_reduce1<<<dim3(10, NG), 128>>>();
    k_finalize<<<8, 32>>>(bias);
    k_router<<<NTOK / 32, 256>>>(x, alpha, beta, out);
}

// round 5
// speedup vs baseline: 1.3846x; 1.3846x over previous
#include <cuda_runtime.h>
#include <math.h>

#define D_DIM 1024
#define F_DIM 4096
#define E_DIM 8
#define NTOK  16384               // B*S
#define NSM   148                 // one CTA per SM for kernel A

// ---------------- device scratch ----------------
__device__ __align__(16) float g_part[NSM][5][D_DIM];   // 3.0 MB
__device__ __align__(16) float g_sum [5][D_DIM];        // raw sums
__device__ __align__(16) float g_stats[5][D_DIM];       // mb, md, cbb, cbd, cdd
__device__ float g_bias_mean;

typedef unsigned long long u64;

__device__ __forceinline__ u64 fma2(u64 a, u64 b, u64 c) {
    u64 d;
    asm("fma.rn.f32x2 %0, %1, %2, %3;" : "=l"(d) : "l"(a), "l"(b), "l"(c));
    return d;
}
__device__ __forceinline__ u64 mul2(u64 a, u64 b) {
    u64 d;
    asm("mul.rn.f32x2 %0, %1, %2;" : "=l"(d) : "l"(a), "l"(b));
    return d;
}
__device__ __forceinline__ float f2lo(u64 v) { return __uint_as_float((unsigned)v); }
__device__ __forceinline__ float f2hi(u64 v) { return __uint_as_float((unsigned)(v >> 32)); }

__device__ __forceinline__ void acc4(float4& s, float4 v)           { s.x += v.x; s.y += v.y; s.z += v.z; s.w += v.w; }
__device__ __forceinline__ void fma4(float4& s, float4 a, float4 b) { s.x = fmaf(a.x,b.x,s.x); s.y = fmaf(a.y,b.y,s.y); s.z = fmaf(a.z,b.z,s.z); s.w = fmaf(a.w,b.w,s.w); }

// ---------------- kernel A: W moments, single wave ------------------------
// grid 148, block 256 (thread = one float4 column). Each CTA strides rows
// by 148 -> ~28 rows x 2 matrices = 56 independent LDG.128 per thread.
__global__ void __launch_bounds__(256) k_reduceW(const float* __restrict__ Wb,
                                                 const float* __restrict__ Wd) {
    const int q = threadIdx.x;                  // float4 column 0..255
    const float4* wb4 = reinterpret_cast<const float4*>(Wb);
    const float4* wd4 = reinterpret_cast<const float4*>(Wd);
    float4 sb = {0,0,0,0}, sd = {0,0,0,0}, sbb = {0,0,0,0}, sbd = {0,0,0,0}, sdd = {0,0,0,0};
#pragma unroll 4
    for (int r = blockIdx.x; r < F_DIM; r += NSM) {
        const size_t base = (size_t)r * 256 + q;
        float4 b = wb4[base];
        float4 w = wd4[base];
        acc4(sb, b); acc4(sd, w);
        fma4(sbb, b, b); fma4(sbd, b, w); fma4(sdd, w, w);
    }
    const int c = blockIdx.x;
    *reinterpret_cast<float4*>(&g_part[c][0][q*4]) = sb;
    *reinterpret_cast<float4*>(&g_part[c][1][q*4]) = sd;
    *reinterpret_cast<float4*>(&g_part[c][2][q*4]) = sbb;
    *reinterpret_cast<float4*>(&g_part[c][3][q*4]) = sbd;
    *reinterpret_cast<float4*>(&g_part[c][4][q*4]) = sdd;
}

// ---------------- kernel B1: reduce 148 partials ---------------------------
// grid (4 colblocks, 5 stats), block 256. Thread sums 148 coalesced scalars.
__global__ void __launch_bounds__(256) k_sum(void) {
    const int d = blockIdx.x * 256 + threadIdx.x;
    const int k = blockIdx.y;
    float s = 0.f;
#pragma unroll 4
    for (int c = 0; c < NSM; c++)
        s += g_part[c][k][d];
    g_sum[k][d] = s;
}

// ---------------- kernel B2: center stats + bias mean ----------------------
// grid 4, block 256.
__global__ void __launch_bounds__(256) k_center(const float* __restrict__ bias) {
    const int d = blockIdx.x * 256 + threadIdx.x;
    const float inv = 1.0f / (float)F_DIM;
    float mb  = g_sum[0][d] * inv;
    float md  = g_sum[1][d] * inv;
    float ebb = g_sum[2][d] * inv;
    float ebd = g_sum[3][d] * inv;
    float edd = g_sum[4][d] * inv;
    g_stats[0][d] = mb;
    g_stats[1][d] = md;
    g_stats[2][d] = ebb - mb * mb;
    g_stats[3][d] = ebd - mb * md;
    g_stats[4][d] = edd - md * md;

    if (blockIdx.x == 0) {
        __shared__ float sh[8];
        const float4* b4 = reinterpret_cast<const float4*>(bias);
        float s = 0.f;
#pragma unroll
        for (int i = 0; i < 4; i++) {
            float4 v = b4[threadIdx.x + i * 256];
            s += (v.x + v.y) + (v.z + v.w);
        }
#pragma unroll
        for (int o = 16; o > 0; o >>= 1) s += __shfl_xor_sync(0xffffffffu, s, o);
        if ((threadIdx.x & 31) == 0) sh[threadIdx.x >> 5] = s;
        __syncthreads();
        if (threadIdx.x == 0) {
            float t = 0.f;
#pragma unroll
            for (int i = 0; i < 8; i++) t += sh[i];
            g_bias_mean = t * inv;
        }
    }
}

// ---------------- kernel C: fused router (5-dot, R2 shape + pipeline) ------
// 128-thread blocks, warp handles 4 tokens, u64 packed FMA accumulators,
// NO register cap, explicit next-chunk prefetch for guaranteed MLP.
__global__ void k_router(const float* __restrict__ x,
                         const float* __restrict__ alpha,
                         const float* __restrict__ beta,
                         float* __restrict__ out) {
    __shared__ float sred[4][4][5];

    const int lane = threadIdx.x & 31;
    const int wid  = threadIdx.x >> 5;
    const int tok0 = (blockIdx.x * 4 + wid) * 4;
    const float* xp = x + (size_t)tok0 * D_DIM;

    u64 acc[4][5];
#pragma unroll
    for (int t = 0; t < 4; t++)
#pragma unroll
        for (int s = 0; s < 5; s++) acc[t][s] = 0ull;

    // prologue: chunk 0 x-loads in flight
    ulonglong2 cur[4];
    {
        const int off = lane * 4;
#pragma unroll
        for (int t = 0; t < 4; t++)
            cur[t] = *reinterpret_cast<const ulonglong2*>(xp + (size_t)t * D_DIM + off);
    }

#pragma unroll
    for (int c = 0; c < 8; c++) {
        const int off = c * 128 + lane * 4;
        // prefetch next chunk before consuming current
        ulonglong2 nxt[4];
        if (c < 7) {
            const int noff = off + 128;
#pragma unroll
            for (int t = 0; t < 4; t++)
                nxt[t] = *reinterpret_cast<const ulonglong2*>(xp + (size_t)t * D_DIM + noff);
        }
        ulonglong2 sv0 = *reinterpret_cast<const ulonglong2*>(&g_stats[0][off]);
        ulonglong2 sv1 = *reinterpret_cast<const ulonglong2*>(&g_stats[1][off]);
        ulonglong2 sv2 = *reinterpret_cast<const ulonglong2*>(&g_stats[2][off]);
        ulonglong2 sv3 = *reinterpret_cast<const ulonglong2*>(&g_stats[3][off]);
        ulonglong2 sv4 = *reinterpret_cast<const ulonglong2*>(&g_stats[4][off]);
#pragma unroll
        for (int t = 0; t < 4; t++) {
            ulonglong2 xv = cur[t];
            u64 xs0 = mul2(xv.x, xv.x);
            u64 xs1 = mul2(xv.y, xv.y);
            acc[t][0] = fma2(xv.x, sv0.x, acc[t][0]);
            acc[t][0] = fma2(xv.y, sv0.y, acc[t][0]);
            acc[t][1] = fma2(xv.x, sv1.x, acc[t][1]);
            acc[t][1] = fma2(xv.y, sv1.y, acc[t][1]);
            acc[t][2] = fma2(xs0,  sv2.x, acc[t][2]);
            acc[t][2] = fma2(xs1,  sv2.y, acc[t][2]);
            acc[t][3] = fma2(xs0,  sv3.x, acc[t][3]);
            acc[t][3] = fma2(xs1,  sv3.y, acc[t][3]);
            acc[t][4] = fma2(xs0,  sv4.x, acc[t][4]);
            acc[t][4] = fma2(xs1,  sv4.y, acc[t][4]);
        }
#pragma unroll
        for (int t = 0; t < 4; t++) cur[t] = nxt[t];
    }

    // warp reductions: 20 scalars, unique landing lane per (t,s)
#pragma unroll
    for (int t = 0; t < 4; t++) {
#pragma unroll
        for (int s = 0; s < 5; s++) {
            float v = f2lo(acc[t][s]) + f2hi(acc[t][s]);
#pragma unroll
            for (int o = 16; o > 0; o >>= 1)
                v += __shfl_xor_sync(0xffffffffu, v, o);
            if (lane == t * 5 + s) sred[wid][t][s] = v;
        }
    }
    __syncthreads();

    // epilogue: one thread per token (16 tokens/block)
    if (threadIdx.x < 16) {
        const int w = threadIdx.x >> 2;
        const int t = threadIdx.x & 3;
        const int tok = blockIdx.x * 16 + threadIdx.x;
        const float bm = g_bias_mean;

        const float d_mb = sred[w][t][0];
        const float d_md = sred[w][t][1];
        const float d_bb = sred[w][t][2];
        const float d_bd = sred[w][t][3];
        const float d_dd = sred[w][t][4];

        float l[E_DIM];
#pragma unroll
        for (int e = 0; e < E_DIM; e++) {
            float a = __ldg(&alpha[e]);
            float b = __ldg(&beta[e]);
            float mu = fmaf(a, d_mb, fmaf(b, d_md, bm));
            float va = fmaf(a * a, d_bb, fmaf(2.0f * a * b, d_bd, b * b * d_dd));
            float z  = mu * rsqrtf(va + 1e-8f) * 0.70710678118654752f;
            l[e] = erff(z);
        }

        // top-2 (strict >, ties keep lower index — matches lax.top_k)
        int i1 = -1, i2 = -1;
        float v1 = -2.0f, v2 = -2.0f;
#pragma unroll
        for (int e = 0; e < E_DIM; e++) {
            float val = l[e];
            if (val > v1)      { v2 = v1; i2 = i1; v1 = val; i1 = e; }
            else if (val > v2) { v2 = val; i2 = e; }
        }
        float w2 = 1.0f / (1.0f + expf(v1 - v2));
        float w1 = 1.0f - w2;

        float wv[E_DIM];
#pragma unroll
        for (int e = 0; e < E_DIM; e++)
            wv[e] = (e == i1) ? w1 : ((e == i2) ? w2 : 0.0f);

        float4* ow = reinterpret_cast<float4*>(out + (size_t)tok * E_DIM);
        ow[0] = make_float4(wv[0], wv[1], wv[2], wv[3]);
        ow[1] = make_float4(wv[4], wv[5], wv[6], wv[7]);
        float4* ol = reinterpret_cast<float4*>(out + (size_t)NTOK * E_DIM + (size_t)tok * E_DIM);
        ol[0] = make_float4(l[0], l[1], l[2], l[3]);
        ol[1] = make_float4(l[4], l[5], l[6], l[7]);
    }
}

// ---------------- launch ---------------------------------------------------
extern "C" void kernel_launch(void* const* d_in, const int* in_sizes, int n_in,
                              void* d_out, int out_size) {
    const float* x     = (const float*)d_in[0];
    const float* Wb    = (const float*)d_in[1];
    const float* Wd    = (const float*)d_in[2];
    const float* bias  = (const float*)d_in[3];
    const float* alpha = (const float*)d_in[4];
    const float* beta  = (const float*)d_in[5];
    float* out = (float*)d_out;

    k_reduceW<<<NSM, 256>>>(Wb, Wd);
    k_sum<<<dim3(4, 5), 256>>>();
    k_center<<<4, 256>>>(bias);
    k_router<<<NTOK / 16, 128>>>(x, alpha, beta, out);
}

// round 6
// speedup vs baseline: 1.6241x; 1.1730x over previous
#include <cuda_runtime.h>
#include <math.h>

#define D_DIM 1024
#define F_DIM 4096
#define E_DIM 8
#define NTOK  16384               // B*S
#define NSM   148                 // one CTA per SM for kernel A
#define NG    8                   // groups for stage-1 partial reduce
#define CH_PER_G 19               // ceil(148/8)

// ---------------- device scratch ----------------
__device__ __align__(16) float g_part[NSM][5][D_DIM];   // 3.0 MB
__device__ __align__(16) float g_sum2[NG][5][D_DIM];    // group sums
__device__ __align__(16) float g_stats[5][D_DIM];       // mb, md, cbb, cbd, cdd
__device__ float g_bias_mean;

typedef unsigned long long u64;

__device__ __forceinline__ u64 fma2(u64 a, u64 b, u64 c) {
    u64 d;
    asm("fma.rn.f32x2 %0, %1, %2, %3;" : "=l"(d) : "l"(a), "l"(b), "l"(c));
    return d;
}
__device__ __forceinline__ u64 mul2(u64 a, u64 b) {
    u64 d;
    asm("mul.rn.f32x2 %0, %1, %2;" : "=l"(d) : "l"(a), "l"(b));
    return d;
}
__device__ __forceinline__ float f2lo(u64 v) { return __uint_as_float((unsigned)v); }
__device__ __forceinline__ float f2hi(u64 v) { return __uint_as_float((unsigned)(v >> 32)); }

__device__ __forceinline__ void acc4(float4& s, float4 v)           { s.x += v.x; s.y += v.y; s.z += v.z; s.w += v.w; }
__device__ __forceinline__ void fma4(float4& s, float4 a, float4 b) { s.x = fmaf(a.x,b.x,s.x); s.y = fmaf(a.y,b.y,s.y); s.z = fmaf(a.z,b.z,s.z); s.w = fmaf(a.w,b.w,s.w); }

// ---------------- kernel A: W moments, single wave ------------------------
// grid 148, block 256 (thread = one float4 column). Rows strided by 148.
__global__ void __launch_bounds__(256) k_reduceW(const float* __restrict__ Wb,
                                                 const float* __restrict__ Wd) {
    const int q = threadIdx.x;                  // float4 column 0..255
    const float4* wb4 = reinterpret_cast<const float4*>(Wb);
    const float4* wd4 = reinterpret_cast<const float4*>(Wd);
    float4 sb = {0,0,0,0}, sd = {0,0,0,0}, sbb = {0,0,0,0}, sbd = {0,0,0,0}, sdd = {0,0,0,0};
#pragma unroll 4
    for (int r = blockIdx.x; r < F_DIM; r += NSM) {
        const size_t base = (size_t)r * 256 + q;
        float4 b = wb4[base];
        float4 w = wd4[base];
        acc4(sb, b); acc4(sd, w);
        fma4(sbb, b, b); fma4(sbd, b, w); fma4(sdd, w, w);
    }
    const int c = blockIdx.x;
    *reinterpret_cast<float4*>(&g_part[c][0][q*4]) = sb;
    *reinterpret_cast<float4*>(&g_part[c][1][q*4]) = sd;
    *reinterpret_cast<float4*>(&g_part[c][2][q*4]) = sbb;
    *reinterpret_cast<float4*>(&g_part[c][3][q*4]) = sbd;
    *reinterpret_cast<float4*>(&g_part[c][4][q*4]) = sdd;
}

// ---------------- kernel B1: stage-1 group reduce (parallel) ---------------
// grid (2, 5, NG), block 128. Thread = one float4 column; 19 independent
// float4 loads -> deep MLP. 80 blocks total.
__global__ void __launch_bounds__(128) k_sum(void) {
    const int q = blockIdx.x * 128 + threadIdx.x;   // f4col 0..255
    const int k = blockIdx.y;                        // stat
    const int g = blockIdx.z;                        // group
    const int c0 = g * CH_PER_G;
    const int c1 = (c0 + CH_PER_G < NSM) ? c0 + CH_PER_G : NSM;
    float4 s = make_float4(0, 0, 0, 0);
    for (int c = c0; c < c1; c++)
        acc4(s, *reinterpret_cast<const float4*>(&g_part[c][k][q * 4]));
    *reinterpret_cast<float4*>(&g_sum2[g][k][q * 4]) = s;
}

// ---------------- kernel B2: final sum + center + bias mean ----------------
// grid 4, block 256. Thread = one d; 40 coalesced loads.
__global__ void __launch_bounds__(256) k_center(const float* __restrict__ bias) {
    const int d = blockIdx.x * 256 + threadIdx.x;
    float s0 = 0.f, s1 = 0.f, s2 = 0.f, s3 = 0.f, s4 = 0.f;
#pragma unroll
    for (int g = 0; g < NG; g++) {
        s0 += g_sum2[g][0][d];
        s1 += g_sum2[g][1][d];
        s2 += g_sum2[g][2][d];
        s3 += g_sum2[g][3][d];
        s4 += g_sum2[g][4][d];
    }
    const float inv = 1.0f / (float)F_DIM;
    float mb = s0 * inv, md = s1 * inv;
    g_stats[0][d] = mb;
    g_stats[1][d] = md;
    g_stats[2][d] = s2 * inv - mb * mb;
    g_stats[3][d] = s3 * inv - mb * md;
    g_stats[4][d] = s4 * inv - md * md;

    if (blockIdx.x == 0) {
        __shared__ float sh[8];
        const float4* b4 = reinterpret_cast<const float4*>(bias);
        float s = 0.f;
#pragma unroll
        for (int i = 0; i < 4; i++) {
            float4 v = b4[threadIdx.x + i * 256];
            s += (v.x + v.y) + (v.z + v.w);
        }
#pragma unroll
        for (int o = 16; o > 0; o >>= 1) s += __shfl_xor_sync(0xffffffffu, s, o);
        if ((threadIdx.x & 31) == 0) sh[threadIdx.x >> 5] = s;
        __syncthreads();
        if (threadIdx.x == 0) {
            float t = 0.f;
#pragma unroll
            for (int i = 0; i < 8; i++) t += sh[i];
            g_bias_mean = t * inv;
        }
    }
}

// ---------------- kernel C: fused router (smem stats, prefetch-2) ----------
// 128-thread blocks, warp = 4 tokens, u64 packed FMAs, stats in shared,
// two chunks of x in flight per warp (8 LDG.128).
__global__ void k_router(const float* __restrict__ x,
                         const float* __restrict__ alpha,
                         const float* __restrict__ beta,
                         float* __restrict__ out) {
    __shared__ __align__(16) float sh[5][D_DIM];     // 20 KB
    __shared__ float sred[4][4][5];

    // cooperative stats load: 128 threads x 10 float4
    {
#pragma unroll
        for (int k = 0; k < 5; k++) {
#pragma unroll
            for (int j = 0; j < 2; j++) {
                const int q = threadIdx.x + j * 128;   // f4col
                *reinterpret_cast<float4*>(&sh[k][q * 4]) =
                    *reinterpret_cast<const float4*>(&g_stats[k][q * 4]);
            }
        }
    }
    __syncthreads();

    const int lane = threadIdx.x & 31;
    const int wid  = threadIdx.x >> 5;
    const int tok0 = (blockIdx.x * 4 + wid) * 4;
    const float* xp = x + (size_t)tok0 * D_DIM;

    u64 acc[4][5];
#pragma unroll
    for (int t = 0; t < 4; t++)
#pragma unroll
        for (int s = 0; s < 5; s++) acc[t][s] = 0ull;

    // prologue: chunks 0 and 1 in flight
    ulonglong2 buf[2][4];
#pragma unroll
    for (int p = 0; p < 2; p++)
#pragma unroll
        for (int t = 0; t < 4; t++)
            buf[p][t] = *reinterpret_cast<const ulonglong2*>(
                xp + (size_t)t * D_DIM + p * 128 + lane * 4);

#pragma unroll
    for (int c = 0; c < 8; c++) {
        const int off = c * 128 + lane * 4;
        ulonglong2 xv[4];
#pragma unroll
        for (int t = 0; t < 4; t++) xv[t] = buf[c & 1][t];
        // prefetch chunk c+2 into the slot just vacated
        if (c < 6) {
            const int noff = off + 256;
#pragma unroll
            for (int t = 0; t < 4; t++)
                buf[c & 1][t] = *reinterpret_cast<const ulonglong2*>(
                    xp + (size_t)t * D_DIM + noff);
        }
        // stats from shared
        ulonglong2 sv0 = *reinterpret_cast<const ulonglong2*>(&sh[0][off]);
        ulonglong2 sv1 = *reinterpret_cast<const ulonglong2*>(&sh[1][off]);
        ulonglong2 sv2 = *reinterpret_cast<const ulonglong2*>(&sh[2][off]);
        ulonglong2 sv3 = *reinterpret_cast<const ulonglong2*>(&sh[3][off]);
        ulonglong2 sv4 = *reinterpret_cast<const ulonglong2*>(&sh[4][off]);
#pragma unroll
        for (int t = 0; t < 4; t++) {
            u64 xs0 = mul2(xv[t].x, xv[t].x);
            u64 xs1 = mul2(xv[t].y, xv[t].y);
            acc[t][0] = fma2(xv[t].x, sv0.x, acc[t][0]);
            acc[t][0] = fma2(xv[t].y, sv0.y, acc[t][0]);
            acc[t][1] = fma2(xv[t].x, sv1.x, acc[t][1]);
            acc[t][1] = fma2(xv[t].y, sv1.y, acc[t][1]);
            acc[t][2] = fma2(xs0,  sv2.x, acc[t][2]);
            acc[t][2] = fma2(xs1,  sv2.y, acc[t][2]);
            acc[t][3] = fma2(xs0,  sv3.x, acc[t][3]);
            acc[t][3] = fma2(xs1,  sv3.y, acc[t][3]);
            acc[t][4] = fma2(xs0,  sv4.x, acc[t][4]);
            acc[t][4] = fma2(xs1,  sv4.y, acc[t][4]);
        }
    }

    // warp reductions: 20 scalars, unique landing lane per (t,s)
#pragma unroll
    for (int t = 0; t < 4; t++) {
#pragma unroll
        for (int s = 0; s < 5; s++) {
            float v = f2lo(acc[t][s]) + f2hi(acc[t][s]);
#pragma unroll
            for (int o = 16; o > 0; o >>= 1)
                v += __shfl_xor_sync(0xffffffffu, v, o);
            if (lane == t * 5 + s) sred[wid][t][s] = v;
        }
    }
    __syncthreads();

    // epilogue: one thread per token (16 tokens/block)
    if (threadIdx.x < 16) {
        const int w = threadIdx.x >> 2;
        const int t = threadIdx.x & 3;
        const int tok = blockIdx.x * 16 + threadIdx.x;
        const float bm = g_bias_mean;

        const float d_mb = sred[w][t][0];
        const float d_md = sred[w][t][1];
        const float d_bb = sred[w][t][2];
        const float d_bd = sred[w][t][3];
        const float d_dd = sred[w][t][4];

        float l[E_DIM];
#pragma unroll
        for (int e = 0; e < E_DIM; e++) {
            float a = __ldg(&alpha[e]);
            float b = __ldg(&beta[e]);
            float mu = fmaf(a, d_mb, fmaf(b, d_md, bm));
            float va = fmaf(a * a, d_bb, fmaf(2.0f * a * b, d_bd, b * b * d_dd));
            float z  = mu * rsqrtf(va + 1e-8f) * 0.70710678118654752f;
            l[e] = erff(z);
        }

        // top-2 (strict >, ties keep lower index — matches lax.top_k)
        int i1 = -1, i2 = -1;
        float v1 = -2.0f, v2 = -2.0f;
#pragma unroll
        for (int e = 0; e < E_DIM; e++) {
            float val = l[e];
            if (val > v1)      { v2 = v1; i2 = i1; v1 = val; i1 = e; }
            else if (val > v2) { v2 = val; i2 = e; }
        }
        float w2 = 1.0f / (1.0f + expf(v1 - v2));
        float w1 = 1.0f - w2;

        float wv[E_DIM];
#pragma unroll
        for (int e = 0; e < E_DIM; e++)
            wv[e] = (e == i1) ? w1 : ((e == i2) ? w2 : 0.0f);

        float4* ow = reinterpret_cast<float4*>(out + (size_t)tok * E_DIM);
        ow[0] = make_float4(wv[0], wv[1], wv[2], wv[3]);
        ow[1] = make_float4(wv[4], wv[5], wv[6], wv[7]);
        float4* ol = reinterpret_cast<float4*>(out + (size_t)NTOK * E_DIM + (size_t)tok * E_DIM);
        ol[0] = make_float4(l[0], l[1], l[2], l[3]);
        ol[1] = make_float4(l[4], l[5], l[6], l[7]);
    }
}

// ---------------- launch ---------------------------------------------------
extern "C" void kernel_launch(void* const* d_in, const int* in_sizes, int n_in,
                              void* d_out, int out_size) {
    const float* x     = (const float*)d_in[0];
    const float* Wb    = (const float*)d_in[1];
    const float* Wd    = (const float*)d_in[2];
    const float* bias  = (const float*)d_in[3];
    const float* alpha = (const float*)d_in[4];
    const float* beta  = (const float*)d_in[5];
    float* out = (float*)d_out;

    k_reduceW<<<NSM, 256>>>(Wb, Wd);
    k_sum<<<dim3(2, 5, NG), 128>>>();
    k_center<<<4, 256>>>(bias);
    k_router<<<NTOK / 16, 128>>>(x, alpha, beta, out);
}

// round 7
// speedup vs baseline: 1.7257x; 1.0626x over previous
#include <cuda_runtime.h>
#include <math.h>

#define D_DIM 1024
#define F_DIM 4096
#define E_DIM 8
#define NTOK  16384               // B*S
#define NSM   148                 // one CTA per SM for kernel A
#define NG    8                   // groups for stage-1 partial reduce
#define CH_PER_G 19               // ceil(148/8)

// ---------------- device scratch ----------------
__device__ __align__(16) float g_part[NSM][5][D_DIM];   // 3.0 MB
__device__ __align__(16) float g_sum2[NG][5][D_DIM];    // group sums
__device__ __align__(16) float g_stats[5][D_DIM];       // mb, md, cbb, cbd, cdd
__device__ float g_bias_mean;

__device__ __forceinline__ void acc4(float4& s, float4 v)           { s.x += v.x; s.y += v.y; s.z += v.z; s.w += v.w; }
__device__ __forceinline__ void fma4(float4& s, float4 a, float4 b) { s.x = fmaf(a.x,b.x,s.x); s.y = fmaf(a.y,b.y,s.y); s.z = fmaf(a.z,b.z,s.z); s.w = fmaf(a.w,b.w,s.w); }
__device__ __forceinline__ float dot4(float4 a, float4 b, float acc) {
    return fmaf(a.x, b.x, fmaf(a.y, b.y, fmaf(a.z, b.z, fmaf(a.w, b.w, acc))));
}

// ---------------- kernel A: W moments, single wave ------------------------
// grid 148, block 256 (thread = one float4 column). Rows strided by 148.
__global__ void __launch_bounds__(256) k_reduceW(const float* __restrict__ Wb,
                                                 const float* __restrict__ Wd) {
    const int q = threadIdx.x;                  // float4 column 0..255
    const float4* wb4 = reinterpret_cast<const float4*>(Wb);
    const float4* wd4 = reinterpret_cast<const float4*>(Wd);
    float4 sb = {0,0,0,0}, sd = {0,0,0,0}, sbb = {0,0,0,0}, sbd = {0,0,0,0}, sdd = {0,0,0,0};
#pragma unroll 4
    for (int r = blockIdx.x; r < F_DIM; r += NSM) {
        const size_t base = (size_t)r * 256 + q;
        float4 b = wb4[base];
        float4 w = wd4[base];
        acc4(sb, b); acc4(sd, w);
        fma4(sbb, b, b); fma4(sbd, b, w); fma4(sdd, w, w);
    }
    const int c = blockIdx.x;
    *reinterpret_cast<float4*>(&g_part[c][0][q*4]) = sb;
    *reinterpret_cast<float4*>(&g_part[c][1][q*4]) = sd;
    *reinterpret_cast<float4*>(&g_part[c][2][q*4]) = sbb;
    *reinterpret_cast<float4*>(&g_part[c][3][q*4]) = sbd;
    *reinterpret_cast<float4*>(&g_part[c][4][q*4]) = sdd;
}

// ---------------- kernel B1: stage-1 group reduce (parallel) ---------------
// grid (2, 5, NG), block 128. Thread = one float4 column; 19 independent
// float4 loads -> deep MLP. 80 blocks total.
__global__ void __launch_bounds__(128) k_sum(void) {
    const int q = blockIdx.x * 128 + threadIdx.x;   // f4col 0..255
    const int k = blockIdx.y;                        // stat
    const int g = blockIdx.z;                        // group
    const int c0 = g * CH_PER_G;
    const int c1 = (c0 + CH_PER_G < NSM) ? c0 + CH_PER_G : NSM;
    float4 s = make_float4(0, 0, 0, 0);
    for (int c = c0; c < c1; c++)
        acc4(s, *reinterpret_cast<const float4*>(&g_part[c][k][q * 4]));
    *reinterpret_cast<float4*>(&g_sum2[g][k][q * 4]) = s;
}

// ---------------- kernel B2: final sum + center + bias mean ----------------
// grid 4, block 256. Thread = one d; 40 coalesced loads.
__global__ void __launch_bounds__(256) k_center(const float* __restrict__ bias) {
    const int d = blockIdx.x * 256 + threadIdx.x;
    float s0 = 0.f, s1 = 0.f, s2 = 0.f, s3 = 0.f, s4 = 0.f;
#pragma unroll
    for (int g = 0; g < NG; g++) {
        s0 += g_sum2[g][0][d];
        s1 += g_sum2[g][1][d];
        s2 += g_sum2[g][2][d];
        s3 += g_sum2[g][3][d];
        s4 += g_sum2[g][4][d];
    }
    const float inv = 1.0f / (float)F_DIM;
    float mb = s0 * inv, md = s1 * inv;
    g_stats[0][d] = mb;
    g_stats[1][d] = md;
    g_stats[2][d] = s2 * inv - mb * mb;
    g_stats[3][d] = s3 * inv - mb * md;
    g_stats[4][d] = s4 * inv - md * md;

    if (blockIdx.x == 0) {
        __shared__ float sh[8];
        const float4* b4 = reinterpret_cast<const float4*>(bias);
        float s = 0.f;
#pragma unroll
        for (int i = 0; i < 4; i++) {
            float4 v = b4[threadIdx.x + i * 256];
            s += (v.x + v.y) + (v.z + v.w);
        }
#pragma unroll
        for (int o = 16; o > 0; o >>= 1) s += __shfl_xor_sync(0xffffffffu, s, o);
        if ((threadIdx.x & 31) == 0) sh[threadIdx.x >> 5] = s;
        __syncthreads();
        if (threadIdx.x == 0) {
            float t = 0.f;
#pragma unroll
            for (int i = 0; i < 8; i++) t += sh[i];
            g_bias_mean = t * inv;
        }
    }
}

// ---------------- kernel C: fused router (8 tokens/warp) -------------------
// 128-thread blocks (4 warps), warp = 8 tokens => 8 LDG.128 (4KB) in flight
// per warp, double-buffered. Scalar FFMA accumulators, stats in shared.
__global__ void k_router(const float* __restrict__ x,
                         const float* __restrict__ alpha,
                         const float* __restrict__ beta,
                         float* __restrict__ out) {
    __shared__ __align__(16) float sh[5][D_DIM];     // 20 KB
    __shared__ float sred[4][8][5];

    // cooperative stats load: 128 threads x 10 float4
    {
#pragma unroll
        for (int k = 0; k < 5; k++) {
#pragma unroll
            for (int j = 0; j < 2; j++) {
                const int q = threadIdx.x + j * 128;
                *reinterpret_cast<float4*>(&sh[k][q * 4]) =
                    *reinterpret_cast<const float4*>(&g_stats[k][q * 4]);
            }
        }
    }
    __syncthreads();

    const int lane = threadIdx.x & 31;
    const int wid  = threadIdx.x >> 5;
    const int tok0 = (blockIdx.x * 4 + wid) * 8;
    const float* xp = x + (size_t)tok0 * D_DIM + lane * 4;

    float acc[8][5];
#pragma unroll
    for (int t = 0; t < 8; t++)
#pragma unroll
        for (int s = 0; s < 5; s++) acc[t][s] = 0.f;

    // preload chunk 0: 8 independent LDG.128
    float4 buf[8];
#pragma unroll
    for (int t = 0; t < 8; t++)
        buf[t] = *reinterpret_cast<const float4*>(xp + (size_t)t * D_DIM);

#pragma unroll
    for (int c = 0; c < 8; c++) {
        float4 cur[8];
#pragma unroll
        for (int t = 0; t < 8; t++) cur[t] = buf[t];
        if (c < 7) {
            const int noff = (c + 1) * 128;
#pragma unroll
            for (int t = 0; t < 8; t++)
                buf[t] = *reinterpret_cast<const float4*>(xp + (size_t)t * D_DIM + noff);
        }
        const int off = c * 128 + lane * 4;
        float4 s0 = *reinterpret_cast<const float4*>(&sh[0][off]);
        float4 s1 = *reinterpret_cast<const float4*>(&sh[1][off]);
        float4 s2 = *reinterpret_cast<const float4*>(&sh[2][off]);
        float4 s3 = *reinterpret_cast<const float4*>(&sh[3][off]);
        float4 s4 = *reinterpret_cast<const float4*>(&sh[4][off]);
#pragma unroll
        for (int t = 0; t < 8; t++) {
            float4 v = cur[t];
            float4 q;
            q.x = v.x * v.x; q.y = v.y * v.y; q.z = v.z * v.z; q.w = v.w * v.w;
            acc[t][0] = dot4(v, s0, acc[t][0]);
            acc[t][1] = dot4(v, s1, acc[t][1]);
            acc[t][2] = dot4(q, s2, acc[t][2]);
            acc[t][3] = dot4(q, s3, acc[t][3]);
            acc[t][4] = dot4(q, s4, acc[t][4]);
        }
    }

    // warp reductions: token t's 5 sums land on lane t
#pragma unroll
    for (int t = 0; t < 8; t++) {
        float v0 = acc[t][0], v1 = acc[t][1], v2 = acc[t][2], v3 = acc[t][3], v4 = acc[t][4];
#pragma unroll
        for (int o = 16; o > 0; o >>= 1) {
            v0 += __shfl_xor_sync(0xffffffffu, v0, o);
            v1 += __shfl_xor_sync(0xffffffffu, v1, o);
            v2 += __shfl_xor_sync(0xffffffffu, v2, o);
            v3 += __shfl_xor_sync(0xffffffffu, v3, o);
            v4 += __shfl_xor_sync(0xffffffffu, v4, o);
        }
        if (lane == t) {
            sred[wid][t][0] = v0;
            sred[wid][t][1] = v1;
            sred[wid][t][2] = v2;
            sred[wid][t][3] = v3;
            sred[wid][t][4] = v4;
        }
    }
    __syncthreads();

    // epilogue: one thread per token (32 tokens/block)
    if (threadIdx.x < 32) {
        const int w = threadIdx.x >> 3;
        const int t = threadIdx.x & 7;
        const int tok = blockIdx.x * 32 + threadIdx.x;
        const float bm = g_bias_mean;

        const float d_mb = sred[w][t][0];
        const float d_md = sred[w][t][1];
        const float d_bb = sred[w][t][2];
        const float d_bd = sred[w][t][3];
        const float d_dd = sred[w][t][4];

        float l[E_DIM];
#pragma unroll
        for (int e = 0; e < E_DIM; e++) {
            float a = __ldg(&alpha[e]);
            float b = __ldg(&beta[e]);
            float mu = fmaf(a, d_mb, fmaf(b, d_md, bm));
            float va = fmaf(a * a, d_bb, fmaf(2.0f * a * b, d_bd, b * b * d_dd));
            float z  = mu * rsqrtf(va + 1e-8f) * 0.70710678118654752f;
            l[e] = erff(z);
        }

        // top-2 (strict >, ties keep lower index — matches lax.top_k)
        int i1 = -1, i2 = -1;
        float v1 = -2.0f, v2 = -2.0f;
#pragma unroll
        for (int e = 0; e < E_DIM; e++) {
            float val = l[e];
            if (val > v1)      { v2 = v1; i2 = i1; v1 = val; i1 = e; }
            else if (val > v2) { v2 = val; i2 = e; }
        }
        float w2 = 1.0f / (1.0f + expf(v1 - v2));
        float w1 = 1.0f - w2;

        float wv[E_DIM];
#pragma unroll
        for (int e = 0; e < E_DIM; e++)
            wv[e] = (e == i1) ? w1 : ((e == i2) ? w2 : 0.0f);

        float4* ow = reinterpret_cast<float4*>(out + (size_t)tok * E_DIM);
        ow[0] = make_float4(wv[0], wv[1], wv[2], wv[3]);
        ow[1] = make_float4(wv[4], wv[5], wv[6], wv[7]);
        float4* ol = reinterpret_cast<float4*>(out + (size_t)NTOK * E_DIM + (size_t)tok * E_DIM);
        ol[0] = make_float4(l[0], l[1], l[2], l[3]);
        ol[1] = make_float4(l[4], l[5], l[6], l[7]);
    }
}

// ---------------- launch ---------------------------------------------------
extern "C" void kernel_launch(void* const* d_in, const int* in_sizes, int n_in,
                              void* d_out, int out_size) {
    const float* x     = (const float*)d_in[0];
    const float* Wb    = (const float*)d_in[1];
    const float* Wd    = (const float*)d_in[2];
    const float* bias  = (const float*)d_in[3];
    const float* alpha = (const float*)d_in[4];
    const float* beta  = (const float*)d_in[5];
    float* out = (float*)d_out;

    k_reduceW<<<NSM, 256>>>(Wb, Wd);
    k_sum<<<dim3(2, 5, NG), 128>>>();
    k_center<<<4, 256>>>(bias);
    k_router<<<NTOK / 32, 128>>>(x, alpha, beta, out);
}

// round 10
// speedup vs baseline: 1.8390x; 1.0656x over previous
#include <cuda_runtime.h>
#include <math.h>

#define D_DIM 1024
#define F_DIM 4096
#define E_DIM 8
#define NTOK  16384               // B*S
#define NFB   32                  // f-blocks in kernel A (rows 128 each)
#define NDB   8                   // d-blocks in kernel A (128 floats each)

// ---------------- device scratch ----------------
__device__ __align__(16) float g_part[NFB][5][D_DIM];   // 640 KB
__device__ __align__(16) float g_sum[5][D_DIM];         // raw F-sums
__device__ float g_bias_mean;

__device__ __forceinline__ void acc4(float4& s, float4 v)           { s.x += v.x; s.y += v.y; s.z += v.z; s.w += v.w; }
__device__ __forceinline__ void fma4(float4& s, float4 a, float4 b) { s.x = fmaf(a.x,b.x,s.x); s.y = fmaf(a.y,b.y,s.y); s.z = fmaf(a.z,b.z,s.z); s.w = fmaf(a.w,b.w,s.w); }
__device__ __forceinline__ float dot4(float4 a, float4 b, float acc) {
    return fmaf(a.x, b.x, fmaf(a.y, b.y, fmaf(a.z, b.z, fmaf(a.w, b.w, acc))));
}

// ---------------- kernel A: W moments (2D grid, in-CTA reduce) ------------
// grid (NDB, NFB), block 128. Thread (q = f4col in d-slice, s = row subgroup).
// Each thread: 32 rows x 2 matrices = 64 independent float4 loads.
__global__ void __launch_bounds__(128) k_reduceW(const float* __restrict__ Wb,
                                                 const float* __restrict__ Wd) {
    const int q = threadIdx.x & 31;       // f4col within 128-float d-slice
    const int s = threadIdx.x >> 5;       // row subgroup 0..3
    const int dblk = blockIdx.x;
    const int fblk = blockIdx.y;
    const int qg = dblk * 32 + q;         // global f4col 0..255

    const float4* wb4 = reinterpret_cast<const float4*>(Wb);
    const float4* wd4 = reinterpret_cast<const float4*>(Wd);

    float4 sb = {0,0,0,0}, sd = {0,0,0,0}, sbb = {0,0,0,0}, sbd = {0,0,0,0}, sdd = {0,0,0,0};
#pragma unroll 8
    for (int i = 0; i < 32; i++) {
        const int r = fblk * 128 + s + i * 4;
        const size_t base = (size_t)r * 256 + qg;
        float4 b = wb4[base];
        float4 w = wd4[base];
        acc4(sb, b); acc4(sd, w);
        fma4(sbb, b, b); fma4(sbd, b, w); fma4(sdd, w, w);
    }

    __shared__ float4 red[4][5][32];
    red[s][0][q] = sb;
    red[s][1][q] = sd;
    red[s][2][q] = sbb;
    red[s][3][q] = sbd;
    red[s][4][q] = sdd;
    __syncthreads();

    if (s == 0) {
#pragma unroll
        for (int k = 0; k < 5; k++) {
            float4 t = red[0][k][q];
            acc4(t, red[1][k][q]);
            acc4(t, red[2][k][q]);
            acc4(t, red[3][k][q]);
            *reinterpret_cast<float4*>(&g_part[fblk][k][qg * 4]) = t;
        }
    }
}

// ---------------- kernel B: reduce 32 partials + bias mean -----------------
// grid (4, 6), block 256. y<5: stat reduce (thread = one d, 32 coalesced
// loads). y==5, x==0: bias mean.
__global__ void __launch_bounds__(256) k_sum(const float* __restrict__ bias) {
    const int k = blockIdx.y;
    if (k < 5) {
        const int d = blockIdx.x * 256 + threadIdx.x;
        float s = 0.f;
#pragma unroll 8
        for (int c = 0; c < NFB; c++)
            s += g_part[c][k][d];
        g_sum[k][d] = s;
    } else if (blockIdx.x == 0) {
        __shared__ float sh[8];
        const float4* b4 = reinterpret_cast<const float4*>(bias);
        float s = 0.f;
#pragma unroll
        for (int i = 0; i < 4; i++) {
            float4 v = b4[threadIdx.x + i * 256];
            s += (v.x + v.y) + (v.z + v.w);
        }
#pragma unroll
        for (int o = 16; o > 0; o >>= 1) s += __shfl_xor_sync(0xffffffffu, s, o);
        if ((threadIdx.x & 31) == 0) sh[threadIdx.x >> 5] = s;
        __syncthreads();
        if (threadIdx.x == 0) {
            float t = 0.f;
#pragma unroll
            for (int i = 0; i < 8; i++) t += sh[i];
            g_bias_mean = t * (1.0f / (float)F_DIM);
        }
    }
}

// ---------------- kernel C: fused router (8 tok/warp, depth-2) -------------
// 128-thread blocks, warp = 8 tokens. Depth-2 software pipeline with slot
// recycling -> up to 16 LDG.128 in flight per warp. Stats centered on the
// fly while staging into shared.
__global__ void k_router(const float* __restrict__ x,
                         const float* __restrict__ alpha,
                         const float* __restrict__ beta,
                         float* __restrict__ out) {
    __shared__ __align__(16) float sh[5][D_DIM];     // 20 KB
    __shared__ float sred[4][8][5];

    // stage raw sums -> centered stats in shared (each block identically)
    {
        const float inv = 1.0f / (float)F_DIM;
#pragma unroll
        for (int j = 0; j < 2; j++) {
            const int q = threadIdx.x + j * 128;     // f4col 0..255
            float4 s0 = *reinterpret_cast<const float4*>(&g_sum[0][q * 4]);
            float4 s1 = *reinterpret_cast<const float4*>(&g_sum[1][q * 4]);
            float4 s2 = *reinterpret_cast<const float4*>(&g_sum[2][q * 4]);
            float4 s3 = *reinterpret_cast<const float4*>(&g_sum[3][q * 4]);
            float4 s4 = *reinterpret_cast<const float4*>(&g_sum[4][q * 4]);
            float4 mb, md, cbb, cbd, cdd;
            mb.x = s0.x*inv; mb.y = s0.y*inv; mb.z = s0.z*inv; mb.w = s0.w*inv;
            md.x = s1.x*inv; md.y = s1.y*inv; md.z = s1.z*inv; md.w = s1.w*inv;
            cbb.x = s2.x*inv - mb.x*mb.x; cbb.y = s2.y*inv - mb.y*mb.y;
            cbb.z = s2.z*inv - mb.z*mb.z; cbb.w = s2.w*inv - mb.w*mb.w;
            cbd.x = s3.x*inv - mb.x*md.x; cbd.y = s3.y*inv - mb.y*md.y;
            cbd.z = s3.z*inv - mb.z*md.z; cbd.w = s3.w*inv - mb.w*md.w;
            cdd.x = s4.x*inv - md.x*md.x; cdd.y = s4.y*inv - md.y*md.y;
            cdd.z = s4.z*inv - md.z*md.z; cdd.w = s4.w*inv - md.w*md.w;
            *reinterpret_cast<float4*>(&sh[0][q * 4]) = mb;
            *reinterpret_cast<float4*>(&sh[1][q * 4]) = md;
            *reinterpret_cast<float4*>(&sh[2][q * 4]) = cbb;
            *reinterpret_cast<float4*>(&sh[3][q * 4]) = cbd;
            *reinterpret_cast<float4*>(&sh[4][q * 4]) = cdd;
        }
    }
    __syncthreads();

    const int lane = threadIdx.x & 31;
    const int wid  = threadIdx.x >> 5;
    const int tok0 = (blockIdx.x * 4 + wid) * 8;
    const float* xp = x + (size_t)tok0 * D_DIM + lane * 4;   // lane offset baked in

    float acc[8][5];
#pragma unroll
    for (int t = 0; t < 8; t++)
#pragma unroll
        for (int s = 0; s < 5; s++) acc[t][s] = 0.f;

    // preload chunks 0 and 1: 16 LDG.128 in flight
    float4 buf[2][8];
#pragma unroll
    for (int p = 0; p < 2; p++)
#pragma unroll
        for (int t = 0; t < 8; t++)
            buf[p][t] = *reinterpret_cast<const float4*>(xp + (size_t)t * D_DIM + p * 128);

#pragma unroll
    for (int c = 0; c < 8; c++) {
        const int off = c * 128 + lane * 4;      // shared-mem offset (lane included)
        const int nchunk = (c + 2) * 128;        // x refill offset (xp has lane*4)
        float4 s0 = *reinterpret_cast<const float4*>(&sh[0][off]);
        float4 s1 = *reinterpret_cast<const float4*>(&sh[1][off]);
        float4 s2 = *reinterpret_cast<const float4*>(&sh[2][off]);
        float4 s3 = *reinterpret_cast<const float4*>(&sh[3][off]);
        float4 s4 = *reinterpret_cast<const float4*>(&sh[4][off]);
#pragma unroll
        for (int t = 0; t < 8; t++) {
            float4 v = buf[c & 1][t];
            // refill slot t with chunk c+2 immediately after last use
            if (c < 6)
                buf[c & 1][t] = *reinterpret_cast<const float4*>(
                    xp + (size_t)t * D_DIM + nchunk);
            float4 q;
            q.x = v.x * v.x; q.y = v.y * v.y; q.z = v.z * v.z; q.w = v.w * v.w;
            acc[t][0] = dot4(v, s0, acc[t][0]);
            acc[t][1] = dot4(v, s1, acc[t][1]);
            acc[t][2] = dot4(q, s2, acc[t][2]);
            acc[t][3] = dot4(q, s3, acc[t][3]);
            acc[t][4] = dot4(q, s4, acc[t][4]);
        }
    }

    // warp reductions: token t's 5 sums land on lane t
#pragma unroll
    for (int t = 0; t < 8; t++) {
        float v0 = acc[t][0], v1 = acc[t][1], v2 = acc[t][2], v3 = acc[t][3], v4 = acc[t][4];
#pragma unroll
        for (int o = 16; o > 0; o >>= 1) {
            v0 += __shfl_xor_sync(0xffffffffu, v0, o);
            v1 += __shfl_xor_sync(0xffffffffu, v1, o);
            v2 += __shfl_xor_sync(0xffffffffu, v2, o);
            v3 += __shfl_xor_sync(0xffffffffu, v3, o);
            v4 += __shfl_xor_sync(0xffffffffu, v4, o);
        }
        if (lane == t) {
            sred[wid][t][0] = v0;
            sred[wid][t][1] = v1;
            sred[wid][t][2] = v2;
            sred[wid][t][3] = v3;
            sred[wid][t][4] = v4;
        }
    }
    __syncthreads();

    // epilogue: one thread per token (32 tokens/block)
    if (threadIdx.x < 32) {
        const int w = threadIdx.x >> 3;
        const int t = threadIdx.x & 7;
        const int tok = blockIdx.x * 32 + threadIdx.x;
        const float bm = g_bias_mean;

        const float d_mb = sred[w][t][0];
        const float d_md = sred[w][t][1];
        const float d_bb = sred[w][t][2];
        const float d_bd = sred[w][t][3];
        const float d_dd = sred[w][t][4];

        float l[E_DIM];
#pragma unroll
        for (int e = 0; e < E_DIM; e++) {
            float a = __ldg(&alpha[e]);
            float b = __ldg(&beta[e]);
            float mu = fmaf(a, d_mb, fmaf(b, d_md, bm));
            float va = fmaf(a * a, d_bb, fmaf(2.0f * a * b, d_bd, b * b * d_dd));
            float z  = mu * rsqrtf(va + 1e-8f) * 0.70710678118654752f;
            l[e] = erff(z);
        }

        // top-2 (strict >, ties keep lower index — matches lax.top_k)
        int i1 = -1, i2 = -1;
        float v1 = -2.0f, v2 = -2.0f;
#pragma unroll
        for (int e = 0; e < E_DIM; e++) {
            float val = l[e];
            if (val > v1)      { v2 = v1; i2 = i1; v1 = val; i1 = e; }
            else if (val > v2) { v2 = val; i2 = e; }
        }
        float w2 = 1.0f / (1.0f + expf(v1 - v2));
        float w1 = 1.0f - w2;

        float wv[E_DIM];
#pragma unroll
        for (int e = 0; e < E_DIM; e++)
            wv[e] = (e == i1) ? w1 : ((e == i2) ? w2 : 0.0f);

        float4* ow = reinterpret_cast<float4*>(out + (size_t)tok * E_DIM);
        ow[0] = make_float4(wv[0], wv[1], wv[2], wv[3]);
        ow[1] = make_float4(wv[4], wv[5], wv[6], wv[7]);
        float4* ol = reinterpret_cast<float4*>(out + (size_t)NTOK * E_DIM + (size_t)tok * E_DIM);
        ol[0] = make_float4(l[0], l[1], l[2], l[3]);
        ol[1] = make_float4(l[4], l[5], l[6], l[7]);
    }
}

// ---------------- launch ---------------------------------------------------
extern "C" void kernel_launch(void* const* d_in, const int* in_sizes, int n_in,
                              void* d_out, int out_size) {
    const float* x     = (const float*)d_in[0];
    const float* Wb    = (const float*)d_in[1];
    const float* Wd    = (const float*)d_in[2];
    const float* bias  = (const float*)d_in[3];
    const float* alpha = (const float*)d_in[4];
    const float* beta  = (const float*)d_in[5];
    float* out = (float*)d_out;

    k_reduceW<<<dim3(NDB, NFB), 128>>>(Wb, Wd);
    k_sum<<<dim3(4, 6), 256>>>(bias);
    k_router<<<NTOK / 32, 128>>>(x, alpha, beta, out);
}

// round 11
// speedup vs baseline: 1.9922x; 1.0833x over previous
#include <cuda_runtime.h>
#include <math.h>

#define D_DIM 1024
#define F_DIM 4096
#define E_DIM 8
#define NTOK  16384               // B*S
#define NFB   128                 // f-blocks in kernel A (32 rows each)
#define ROWS_PER_FB (F_DIM/NFB)   // 32

// ---------------- device scratch ----------------
__device__ __align__(16) float g_part[NFB][5][D_DIM];   // 2.5 MB
__device__ __align__(16) float g_sum[5][D_DIM];         // raw F-sums
__device__ float g_bias_mean;

__device__ __forceinline__ void acc4(float4& s, float4 v)           { s.x += v.x; s.y += v.y; s.z += v.z; s.w += v.w; }
__device__ __forceinline__ void fma4(float4& s, float4 a, float4 b) { s.x = fmaf(a.x,b.x,s.x); s.y = fmaf(a.y,b.y,s.y); s.z = fmaf(a.z,b.z,s.z); s.w = fmaf(a.w,b.w,s.w); }
__device__ __forceinline__ float dot4(float4 a, float4 b, float acc) {
    return fmaf(a.x, b.x, fmaf(a.y, b.y, fmaf(a.z, b.z, fmaf(a.w, b.w, acc))));
}

// ---------------- kernel A: W moments (depth-4 prefetch) -------------------
// grid 128, block 256. Thread = one float4 column; CTA = 32 contiguous rows.
// Explicit 4-row double buffer -> 8 LDG.128 in flight per thread.
__global__ void __launch_bounds__(256) k_reduceW(const float* __restrict__ Wb,
                                                 const float* __restrict__ Wd) {
    const int q = threadIdx.x;                  // f4col 0..255
    const size_t base = (size_t)blockIdx.x * ROWS_PER_FB * 256 + q;
    const float4* pb = reinterpret_cast<const float4*>(Wb) + base;
    const float4* pw = reinterpret_cast<const float4*>(Wd) + base;

    float4 sb = {0,0,0,0}, sd = {0,0,0,0}, sbb = {0,0,0,0}, sbd = {0,0,0,0}, sdd = {0,0,0,0};

    // preload rows 0..3 of both matrices: 8 independent LDG.128
    float4 bufb[4], bufw[4];
#pragma unroll
    for (int p = 0; p < 4; p++) {
        bufb[p] = pb[(size_t)p * 256];
        bufw[p] = pw[(size_t)p * 256];
    }

#pragma unroll
    for (int i = 0; i < ROWS_PER_FB; i++) {
        float4 b = bufb[i & 3];
        float4 w = bufw[i & 3];
        if (i < ROWS_PER_FB - 4) {
            bufb[i & 3] = pb[(size_t)(i + 4) * 256];
            bufw[i & 3] = pw[(size_t)(i + 4) * 256];
        }
        acc4(sb, b); acc4(sd, w);
        fma4(sbb, b, b); fma4(sbd, b, w); fma4(sdd, w, w);
    }

    const int c = blockIdx.x;
    *reinterpret_cast<float4*>(&g_part[c][0][q*4]) = sb;
    *reinterpret_cast<float4*>(&g_part[c][1][q*4]) = sd;
    *reinterpret_cast<float4*>(&g_part[c][2][q*4]) = sbb;
    *reinterpret_cast<float4*>(&g_part[c][3][q*4]) = sbd;
    *reinterpret_cast<float4*>(&g_part[c][4][q*4]) = sdd;
}

// ---------------- kernel B: reduce 128 partials + bias mean ----------------
// grid (8 coltiles, 6), block 256 = 8 chunk-groups x 32 f4cols.
// y<5: each thread sums 16 chunks for its f4col, then smem-reduce 8 groups.
// y==5, x==0: bias mean.
__global__ void __launch_bounds__(256) k_sum(const float* __restrict__ bias) {
    const int k = blockIdx.y;
    if (k < 5) {
        const int lane = threadIdx.x & 31;          // f4col within tile
        const int g    = threadIdx.x >> 5;          // chunk group 0..7
        const int qg   = blockIdx.x * 32 + lane;    // f4col 0..255
        float4 s = make_float4(0, 0, 0, 0);
#pragma unroll
        for (int i = 0; i < 16; i++)
            acc4(s, *reinterpret_cast<const float4*>(&g_part[g * 16 + i][k][qg * 4]));
        __shared__ float4 red[8][32];
        red[g][lane] = s;
        __syncthreads();
        if (g == 0) {
            float4 t = red[0][lane];
#pragma unroll
            for (int j = 1; j < 8; j++) acc4(t, red[j][lane]);
            *reinterpret_cast<float4*>(&g_sum[k][qg * 4]) = t;
        }
    } else if (blockIdx.x == 0) {
        __shared__ float sh[8];
        const float4* b4 = reinterpret_cast<const float4*>(bias);
        float s = 0.f;
#pragma unroll
        for (int i = 0; i < 4; i++) {
            float4 v = b4[threadIdx.x + i * 256];
            s += (v.x + v.y) + (v.z + v.w);
        }
#pragma unroll
        for (int o = 16; o > 0; o >>= 1) s += __shfl_xor_sync(0xffffffffu, s, o);
        if ((threadIdx.x & 31) == 0) sh[threadIdx.x >> 5] = s;
        __syncthreads();
        if (threadIdx.x == 0) {
            float t = 0.f;
#pragma unroll
            for (int i = 0; i < 8; i++) t += sh[i];
            g_bias_mean = t * (1.0f / (float)F_DIM);
        }
    }
}

// ---------------- kernel C: fused router (8 tok/warp, depth-2) -------------
// 128-thread blocks, warp = 8 tokens. Depth-2 software pipeline with slot
// recycling -> up to 16 LDG.128 in flight per warp. Stats centered on the
// fly while staging into shared. (Unchanged from R10 — verified correct.)
__global__ void k_router(const float* __restrict__ x,
                         const float* __restrict__ alpha,
                         const float* __restrict__ beta,
                         float* __restrict__ out) {
    __shared__ __align__(16) float sh[5][D_DIM];     // 20 KB
    __shared__ float sred[4][8][5];

    // stage raw sums -> centered stats in shared (each block identically)
    {
        const float inv = 1.0f / (float)F_DIM;
#pragma unroll
        for (int j = 0; j < 2; j++) {
            const int q = threadIdx.x + j * 128;     // f4col 0..255
            float4 s0 = *reinterpret_cast<const float4*>(&g_sum[0][q * 4]);
            float4 s1 = *reinterpret_cast<const float4*>(&g_sum[1][q * 4]);
            float4 s2 = *reinterpret_cast<const float4*>(&g_sum[2][q * 4]);
            float4 s3 = *reinterpret_cast<const float4*>(&g_sum[3][q * 4]);
            float4 s4 = *reinterpret_cast<const float4*>(&g_sum[4][q * 4]);
            float4 mb, md, cbb, cbd, cdd;
            mb.x = s0.x*inv; mb.y = s0.y*inv; mb.z = s0.z*inv; mb.w = s0.w*inv;
            md.x = s1.x*inv; md.y = s1.y*inv; md.z = s1.z*inv; md.w = s1.w*inv;
            cbb.x = s2.x*inv - mb.x*mb.x; cbb.y = s2.y*inv - mb.y*mb.y;
            cbb.z = s2.z*inv - mb.z*mb.z; cbb.w = s2.w*inv - mb.w*mb.w;
            cbd.x = s3.x*inv - mb.x*md.x; cbd.y = s3.y*inv - mb.y*md.y;
            cbd.z = s3.z*inv - mb.z*md.z; cbd.w = s3.w*inv - mb.w*md.w;
            cdd.x = s4.x*inv - md.x*md.x; cdd.y = s4.y*inv - md.y*md.y;
            cdd.z = s4.z*inv - md.z*md.z; cdd.w = s4.w*inv - md.w*md.w;
            *reinterpret_cast<float4*>(&sh[0][q * 4]) = mb;
            *reinterpret_cast<float4*>(&sh[1][q * 4]) = md;
            *reinterpret_cast<float4*>(&sh[2][q * 4]) = cbb;
            *reinterpret_cast<float4*>(&sh[3][q * 4]) = cbd;
            *reinterpret_cast<float4*>(&sh[4][q * 4]) = cdd;
        }
    }
    __syncthreads();

    const int lane = threadIdx.x & 31;
    const int wid  = threadIdx.x >> 5;
    const int tok0 = (blockIdx.x * 4 + wid) * 8;
    const float* xp = x + (size_t)tok0 * D_DIM + lane * 4;   // lane offset baked in

    float acc[8][5];
#pragma unroll
    for (int t = 0; t < 8; t++)
#pragma unroll
        for (int s = 0; s < 5; s++) acc[t][s] = 0.f;

    // preload chunks 0 and 1: 16 LDG.128 in flight
    float4 buf[2][8];
#pragma unroll
    for (int p = 0; p < 2; p++)
#pragma unroll
        for (int t = 0; t < 8; t++)
            buf[p][t] = *reinterpret_cast<const float4*>(xp + (size_t)t * D_DIM + p * 128);

#pragma unroll
    for (int c = 0; c < 8; c++) {
        const int off = c * 128 + lane * 4;      // shared-mem offset (lane included)
        const int nchunk = (c + 2) * 128;        // x refill offset (xp has lane*4)
        float4 s0 = *reinterpret_cast<const float4*>(&sh[0][off]);
        float4 s1 = *reinterpret_cast<const float4*>(&sh[1][off]);
        float4 s2 = *reinterpret_cast<const float4*>(&sh[2][off]);
        float4 s3 = *reinterpret_cast<const float4*>(&sh[3][off]);
        float4 s4 = *reinterpret_cast<const float4*>(&sh[4][off]);
#pragma unroll
        for (int t = 0; t < 8; t++) {
            float4 v = buf[c & 1][t];
            // refill slot t with chunk c+2 immediately after last use
            if (c < 6)
                buf[c & 1][t] = *reinterpret_cast<const float4*>(
                    xp + (size_t)t * D_DIM + nchunk);
            float4 q;
            q.x = v.x * v.x; q.y = v.y * v.y; q.z = v.z * v.z; q.w = v.w * v.w;
            acc[t][0] = dot4(v, s0, acc[t][0]);
            acc[t][1] = dot4(v, s1, acc[t][1]);
            acc[t][2] = dot4(q, s2, acc[t][2]);
            acc[t][3] = dot4(q, s3, acc[t][3]);
            acc[t][4] = dot4(q, s4, acc[t][4]);
        }
    }

    // warp reductions: token t's 5 sums land on lane t
#pragma unroll
    for (int t = 0; t < 8; t++) {
        float v0 = acc[t][0], v1 = acc[t][1], v2 = acc[t][2], v3 = acc[t][3], v4 = acc[t][4];
#pragma unroll
        for (int o = 16; o > 0; o >>= 1) {
            v0 += __shfl_xor_sync(0xffffffffu, v0, o);
            v1 += __shfl_xor_sync(0xffffffffu, v1, o);
            v2 += __shfl_xor_sync(0xffffffffu, v2, o);
            v3 += __shfl_xor_sync(0xffffffffu, v3, o);
            v4 += __shfl_xor_sync(0xffffffffu, v4, o);
        }
        if (lane == t) {
            sred[wid][t][0] = v0;
            sred[wid][t][1] = v1;
            sred[wid][t][2] = v2;
            sred[wid][t][3] = v3;
            sred[wid][t][4] = v4;
        }
    }
    __syncthreads();

    // epilogue: one thread per token (32 tokens/block)
    if (threadIdx.x < 32) {
        const int w = threadIdx.x >> 3;
        const int t = threadIdx.x & 7;
        const int tok = blockIdx.x * 32 + threadIdx.x;
        const float bm = g_bias_mean;

        const float d_mb = sred[w][t][0];
        const float d_md = sred[w][t][1];
        const float d_bb = sred[w][t][2];
        const float d_bd = sred[w][t][3];
        const float d_dd = sred[w][t][4];

        float l[E_DIM];
#pragma unroll
        for (int e = 0; e < E_DIM; e++) {
            float a = __ldg(&alpha[e]);
            float b = __ldg(&beta[e]);
            float mu = fmaf(a, d_mb, fmaf(b, d_md, bm));
            float va = fmaf(a * a, d_bb, fmaf(2.0f * a * b, d_bd, b * b * d_dd));
            float z  = mu * rsqrtf(va + 1e-8f) * 0.70710678118654752f;
            l[e] = erff(z);
        }

        // top-2 (strict >, ties keep lower index — matches lax.top_k)
        int i1 = -1, i2 = -1;
        float v1 = -2.0f, v2 = -2.0f;
#pragma unroll
        for (int e = 0; e < E_DIM; e++) {
            float val = l[e];
            if (val > v1)      { v2 = v1; i2 = i1; v1 = val; i1 = e; }
            else if (val > v2) { v2 = val; i2 = e; }
        }
        float w2 = 1.0f / (1.0f + expf(v1 - v2));
        float w1 = 1.0f - w2;

        float wv[E_DIM];
#pragma unroll
        for (int e = 0; e < E_DIM; e++)
            wv[e] = (e == i1) ? w1 : ((e == i2) ? w2 : 0.0f);

        float4* ow = reinterpret_cast<float4*>(out + (size_t)tok * E_DIM);
        ow[0] = make_float4(wv[0], wv[1], wv[2], wv[3]);
        ow[1] = make_float4(wv[4], wv[5], wv[6], wv[7]);
        float4* ol = reinterpret_cast<float4*>(out + (size_t)NTOK * E_DIM + (size_t)tok * E_DIM);
        ol[0] = make_float4(l[0], l[1], l[2], l[3]);
        ol[1] = make_float4(l[4], l[5], l[6], l[7]);
    }
}

// ---------------- launch ---------------------------------------------------
extern "C" void kernel_launch(void* const* d_in, const int* in_sizes, int n_in,
                              void* d_out, int out_size) {
    const float* x     = (const float*)d_in[0];
    const float* Wb    = (const float*)d_in[1];
    const float* Wd    = (const float*)d_in[2];
    const float* bias  = (const float*)d_in[3];
    const float* alpha = (const float*)d_in[4];
    const float* beta  = (const float*)d_in[5];
    float* out = (float*)d_out;

    k_reduceW<<<NFB, 256>>>(Wb, Wd);
    k_sum<<<dim3(8, 6), 256>>>(bias);
    k_router<<<NTOK / 32, 128>>>(x, alpha, beta, out);
}

// round 12
// speedup vs baseline: 2.1144x; 1.0613x over previous
#include <cuda_runtime.h>
#include <math.h>

#define D_DIM 1024
#define F_DIM 4096
#define E_DIM 8
#define NTOK  16384               // B*S
#define NFB   128                 // f-blocks in kernel A (32 rows each)
#define ROWS_PER_FB 32
#define ROWS_PER_TH 16            // two row-halves per CTA

// ---------------- device scratch ----------------
__device__ __align__(16) float g_part[NFB][5][D_DIM];   // 2.5 MB
__device__ __align__(16) float g_sum[5][D_DIM];         // raw F-sums
__device__ float g_bias_mean;

__device__ __forceinline__ void acc4(float4& s, float4 v)           { s.x += v.x; s.y += v.y; s.z += v.z; s.w += v.w; }
__device__ __forceinline__ void fma4(float4& s, float4 a, float4 b) { s.x = fmaf(a.x,b.x,s.x); s.y = fmaf(a.y,b.y,s.y); s.z = fmaf(a.z,b.z,s.z); s.w = fmaf(a.w,b.w,s.w); }
__device__ __forceinline__ float dot4(float4 a, float4 b, float acc) {
    return fmaf(a.x, b.x, fmaf(a.y, b.y, fmaf(a.z, b.z, fmaf(a.w, b.w, acc))));
}

// ---------------- kernel A: W moments (512 thr, depth-8 prefetch) ----------
// grid 128, block 512. Thread = (row-half h, f4col q); 16 rows x 2 mats = 32
// independent LDG.128, 16 in flight (depth-8 double buffer) = 8KB/warp.
__global__ void __launch_bounds__(512) k_reduceW(const float* __restrict__ Wb,
                                                 const float* __restrict__ Wd) {
    const int q = threadIdx.x & 255;            // f4col 0..255
    const int h = threadIdx.x >> 8;             // row half 0..1
    const size_t base = ((size_t)blockIdx.x * ROWS_PER_FB + h * ROWS_PER_TH) * 256 + q;
    const float4* pb = reinterpret_cast<const float4*>(Wb) + base;
    const float4* pw = reinterpret_cast<const float4*>(Wd) + base;

    float4 sb = {0,0,0,0}, sd = {0,0,0,0}, sbb = {0,0,0,0}, sbd = {0,0,0,0}, sdd = {0,0,0,0};

    // preload rows 0..7 of both matrices: 16 independent LDG.128 in flight
    float4 bufb[8], bufw[8];
#pragma unroll
    for (int p = 0; p < 8; p++) {
        bufb[p] = pb[(size_t)p * 256];
        bufw[p] = pw[(size_t)p * 256];
    }

#pragma unroll
    for (int i = 0; i < ROWS_PER_TH; i++) {
        float4 b = bufb[i & 7];
        float4 w = bufw[i & 7];
        if (i < ROWS_PER_TH - 8) {
            bufb[i & 7] = pb[(size_t)(i + 8) * 256];
            bufw[i & 7] = pw[(size_t)(i + 8) * 256];
        }
        acc4(sb, b); acc4(sd, w);
        fma4(sbb, b, b); fma4(sbd, b, w); fma4(sdd, w, w);
    }

    // combine the two row-halves via smem (one stat at a time, 4KB buffer)
    __shared__ float4 red[256];
    const int c = blockIdx.x;
    float4 part[5] = {sb, sd, sbb, sbd, sdd};
#pragma unroll
    for (int k = 0; k < 5; k++) {
        if (h == 1) red[q] = part[k];
        __syncthreads();
        if (h == 0) {
            float4 t = part[k];
            acc4(t, red[q]);
            *reinterpret_cast<float4*>(&g_part[c][k][q * 4]) = t;
        }
        __syncthreads();
    }
}

// ---------------- kernel B: reduce 128 partials + bias mean ----------------
// grid (8 coltiles, 6), block 256 = 8 chunk-groups x 32 f4cols.
__global__ void __launch_bounds__(256) k_sum(const float* __restrict__ bias) {
    const int k = blockIdx.y;
    if (k < 5) {
        const int lane = threadIdx.x & 31;          // f4col within tile
        const int g    = threadIdx.x >> 5;          // chunk group 0..7
        const int qg   = blockIdx.x * 32 + lane;    // f4col 0..255
        float4 s = make_float4(0, 0, 0, 0);
#pragma unroll
        for (int i = 0; i < 16; i++)
            acc4(s, *reinterpret_cast<const float4*>(&g_part[g * 16 + i][k][qg * 4]));
        __shared__ float4 red[8][32];
        red[g][lane] = s;
        __syncthreads();
        if (g == 0) {
            float4 t = red[0][lane];
#pragma unroll
            for (int j = 1; j < 8; j++) acc4(t, red[j][lane]);
            *reinterpret_cast<float4*>(&g_sum[k][qg * 4]) = t;
        }
    } else if (blockIdx.x == 0) {
        __shared__ float sh[8];
        const float4* b4 = reinterpret_cast<const float4*>(bias);
        float s = 0.f;
#pragma unroll
        for (int i = 0; i < 4; i++) {
            float4 v = b4[threadIdx.x + i * 256];
            s += (v.x + v.y) + (v.z + v.w);
        }
#pragma unroll
        for (int o = 16; o > 0; o >>= 1) s += __shfl_xor_sync(0xffffffffu, s, o);
        if ((threadIdx.x & 31) == 0) sh[threadIdx.x >> 5] = s;
        __syncthreads();
        if (threadIdx.x == 0) {
            float t = 0.f;
#pragma unroll
            for (int i = 0; i < 8; i++) t += sh[i];
            g_bias_mean = t * (1.0f / (float)F_DIM);
        }
    }
}

// ---------------- kernel C: fused router (8 tok/warp, depth-2) -------------
// Unchanged from R10/R11 — verified correct, ~12us @ 52% DRAM.
__global__ void k_router(const float* __restrict__ x,
                         const float* __restrict__ alpha,
                         const float* __restrict__ beta,
                         float* __restrict__ out) {
    __shared__ __align__(16) float sh[5][D_DIM];     // 20 KB
    __shared__ float sred[4][8][5];

    // stage raw sums -> centered stats in shared (each block identically)
    {
        const float inv = 1.0f / (float)F_DIM;
#pragma unroll
        for (int j = 0; j < 2; j++) {
            const int q = threadIdx.x + j * 128;     // f4col 0..255
            float4 s0 = *reinterpret_cast<const float4*>(&g_sum[0][q * 4]);
            float4 s1 = *reinterpret_cast<const float4*>(&g_sum[1][q * 4]);
            float4 s2 = *reinterpret_cast<const float4*>(&g_sum[2][q * 4]);
            float4 s3 = *reinterpret_cast<const float4*>(&g_sum[3][q * 4]);
            float4 s4 = *reinterpret_cast<const float4*>(&g_sum[4][q * 4]);
            float4 mb, md, cbb, cbd, cdd;
            mb.x = s0.x*inv; mb.y = s0.y*inv; mb.z = s0.z*inv; mb.w = s0.w*inv;
            md.x = s1.x*inv; md.y = s1.y*inv; md.z = s1.z*inv; md.w = s1.w*inv;
            cbb.x = s2.x*inv - mb.x*mb.x; cbb.y = s2.y*inv - mb.y*mb.y;
            cbb.z = s2.z*inv - mb.z*mb.z; cbb.w = s2.w*inv - mb.w*mb.w;
            cbd.x = s3.x*inv - mb.x*md.x; cbd.y = s3.y*inv - mb.y*md.y;
            cbd.z = s3.z*inv - mb.z*md.z; cbd.w = s3.w*inv - mb.w*md.w;
            cdd.x = s4.x*inv - md.x*md.x; cdd.y = s4.y*inv - md.y*md.y;
            cdd.z = s4.z*inv - md.z*md.z; cdd.w = s4.w*inv - md.w*md.w;
            *reinterpret_cast<float4*>(&sh[0][q * 4]) = mb;
            *reinterpret_cast<float4*>(&sh[1][q * 4]) = md;
            *reinterpret_cast<float4*>(&sh[2][q * 4]) = cbb;
            *reinterpret_cast<float4*>(&sh[3][q * 4]) = cbd;
            *reinterpret_cast<float4*>(&sh[4][q * 4]) = cdd;
        }
    }
    __syncthreads();

    const int lane = threadIdx.x & 31;
    const int wid  = threadIdx.x >> 5;
    const int tok0 = (blockIdx.x * 4 + wid) * 8;
    const float* xp = x + (size_t)tok0 * D_DIM + lane * 4;   // lane offset baked in

    float acc[8][5];
#pragma unroll
    for (int t = 0; t < 8; t++)
#pragma unroll
        for (int s = 0; s < 5; s++) acc[t][s] = 0.f;

    // preload chunks 0 and 1: 16 LDG.128 in flight
    float4 buf[2][8];
#pragma unroll
    for (int p = 0; p < 2; p++)
#pragma unroll
        for (int t = 0; t < 8; t++)
            buf[p][t] = *reinterpret_cast<const float4*>(xp + (size_t)t * D_DIM + p * 128);

#pragma unroll
    for (int c = 0; c < 8; c++) {
        const int off = c * 128 + lane * 4;      // shared-mem offset (lane included)
        const int nchunk = (c + 2) * 128;        // x refill offset (xp has lane*4)
        float4 s0 = *reinterpret_cast<const float4*>(&sh[0][off]);
        float4 s1 = *reinterpret_cast<const float4*>(&sh[1][off]);
        float4 s2 = *reinterpret_cast<const float4*>(&sh[2][off]);
        float4 s3 = *reinterpret_cast<const float4*>(&sh[3][off]);
        float4 s4 = *reinterpret_cast<const float4*>(&sh[4][off]);
#pragma unroll
        for (int t = 0; t < 8; t++) {
            float4 v = buf[c & 1][t];
            // refill slot t with chunk c+2 immediately after last use
            if (c < 6)
                buf[c & 1][t] = *reinterpret_cast<const float4*>(
                    xp + (size_t)t * D_DIM + nchunk);
            float4 q;
            q.x = v.x * v.x; q.y = v.y * v.y; q.z = v.z * v.z; q.w = v.w * v.w;
            acc[t][0] = dot4(v, s0, acc[t][0]);
            acc[t][1] = dot4(v, s1, acc[t][1]);
            acc[t][2] = dot4(q, s2, acc[t][2]);
            acc[t][3] = dot4(q, s3, acc[t][3]);
            acc[t][4] = dot4(q, s4, acc[t][4]);
        }
    }

    // warp reductions: token t's 5 sums land on lane t
#pragma unroll
    for (int t = 0; t < 8; t++) {
        float v0 = acc[t][0], v1 = acc[t][1], v2 = acc[t][2], v3 = acc[t][3], v4 = acc[t][4];
#pragma unroll
        for (int o = 16; o > 0; o >>= 1) {
            v0 += __shfl_xor_sync(0xffffffffu, v0, o);
            v1 += __shfl_xor_sync(0xffffffffu, v1, o);
            v2 += __shfl_xor_sync(0xffffffffu, v2, o);
            v3 += __shfl_xor_sync(0xffffffffu, v3, o);
            v4 += __shfl_xor_sync(0xffffffffu, v4, o);
        }
        if (lane == t) {
            sred[wid][t][0] = v0;
            sred[wid][t][1] = v1;
            sred[wid][t][2] = v2;
            sred[wid][t][3] = v3;
            sred[wid][t][4] = v4;
        }
    }
    __syncthreads();

    // epilogue: one thread per token (32 tokens/block)
    if (threadIdx.x < 32) {
        const int w = threadIdx.x >> 3;
        const int t = threadIdx.x & 7;
        const int tok = blockIdx.x * 32 + threadIdx.x;
        const float bm = g_bias_mean;

        const float d_mb = sred[w][t][0];
        const float d_md = sred[w][t][1];
        const float d_bb = sred[w][t][2];
        const float d_bd = sred[w][t][3];
        const float d_dd = sred[w][t][4];

        float l[E_DIM];
#pragma unroll
        for (int e = 0; e < E_DIM; e++) {
            float a = __ldg(&alpha[e]);
            float b = __ldg(&beta[e]);
            float mu = fmaf(a, d_mb, fmaf(b, d_md, bm));
            float va = fmaf(a * a, d_bb, fmaf(2.0f * a * b, d_bd, b * b * d_dd));
            float z  = mu * rsqrtf(va + 1e-8f) * 0.70710678118654752f;
            l[e] = erff(z);
        }

        // top-2 (strict >, ties keep lower index — matches lax.top_k)
        int i1 = -1, i2 = -1;
        float v1 = -2.0f, v2 = -2.0f;
#pragma unroll
        for (int e = 0; e < E_DIM; e++) {
            float val = l[e];
            if (val > v1)      { v2 = v1; i2 = i1; v1 = val; i1 = e; }
            else if (val > v2) { v2 = val; i2 = e; }
        }
        float w2 = 1.0f / (1.0f + expf(v1 - v2));
        float w1 = 1.0f - w2;

        float wv[E_DIM];
#pragma unroll
        for (int e = 0; e < E_DIM; e++)
            wv[e] = (e == i1) ? w1 : ((e == i2) ? w2 : 0.0f);

        float4* ow = reinterpret_cast<float4*>(out + (size_t)tok * E_DIM);
        ow[0] = make_float4(wv[0], wv[1], wv[2], wv[3]);
        ow[1] = make_float4(wv[4], wv[5], wv[6], wv[7]);
        float4* ol = reinterpret_cast<float4*>(out + (size_t)NTOK * E_DIM + (size_t)tok * E_DIM);
        ol[0] = make_float4(l[0], l[1], l[2], l[3]);
        ol[1] = make_float4(l[4], l[5], l[6], l[7]);
    }
}

// ---------------- launch ---------------------------------------------------
extern "C" void kernel_launch(void* const* d_in, const int* in_sizes, int n_in,
                              void* d_out, int out_size) {
    const float* x     = (const float*)d_in[0];
    const float* Wb    = (const float*)d_in[1];
    const float* Wd    = (const float*)d_in[2];
    const float* bias  = (const float*)d_in[3];
    const float* alpha = (const float*)d_in[4];
    const float* beta  = (const float*)d_in[5];
    float* out = (float*)d_out;

    k_reduceW<<<NFB, 512>>>(Wb, Wd);
    k_sum<<<dim3(8, 6), 256>>>(bias);
    k_router<<<NTOK / 32, 128>>>(x, alpha, beta, out);
}